// round 17
// baseline (speedup 1.0000x reference)
#include <cuda_runtime.h>
#include <cuda_fp16.h>
#include <cstdint>

// Problem constants
static constexpr int Nb = 4, C = 12, GD = 8, GH = 16, GW = 16;
static constexpr int H = 1024, W = 1024;
static constexpr int HW = H * W;
static constexpr int GRID_PER_N = C * GD * GH * GW;   // 24576 floats

// y-lerped buffer (ONLY smem): [z][x-entry][16 halfs], one image row.
// Entry = 12 data + 4 pad halfs (32 B): corner fetch = LDS.128 + LDS.64 at
// 16B-aligned addresses. z-slab = 16 entries + 8 pad halfs = 264 halfs =
// 132 words == 4 (mod 32): the 8 z levels hit disjoint 4-word bank groups.
static constexpr int ENTRY = 16;
static constexpr int YSLAB = GW * ENTRY + 8;           // 264 halfs
static constexpr int YROW  = GD * YSLAB;               // 2112 halfs
static constexpr int YBUF_HALFS = YROW + 16;           // 2128 halfs
static constexpr int SMEM_BYTES = YBUF_HALFS * 2;      // 4256 B

static constexpr int THREADS = 512;                    // 2 px/thread = full row

__device__ __forceinline__ __half2 u2h(unsigned u) {
    return *reinterpret_cast<__half2*>(&u);
}

// Fetch both x-corners (12 ch each) from a y-lerped slab, x-lerp -> 6 half2.
__device__ __forceinline__ void fetch_xlerp(const __half* buf, int off,
                                            __half2 wx0, __half2 wx1,
                                            __half2* r) {
    uint4 a01 = *reinterpret_cast<const uint4*>(buf + off);
    uint2 a2  = *reinterpret_cast<const uint2*>(buf + off + 8);
    uint4 b01 = *reinterpret_cast<const uint4*>(buf + off + ENTRY);
    uint2 b2  = *reinterpret_cast<const uint2*>(buf + off + ENTRY + 8);
    r[0] = __hfma2(u2h(b01.x), wx1, __hmul2(u2h(a01.x), wx0));
    r[1] = __hfma2(u2h(b01.y), wx1, __hmul2(u2h(a01.y), wx0));
    r[2] = __hfma2(u2h(b01.z), wx1, __hmul2(u2h(a01.z), wx0));
    r[3] = __hfma2(u2h(b01.w), wx1, __hmul2(u2h(a01.w), wx0));
    r[4] = __hfma2(u2h(b2.x),  wx1, __hmul2(u2h(a2.x),  wx0));
    r[5] = __hfma2(u2h(b2.y),  wx1, __hmul2(u2h(a2.y),  wx0));
}

__global__ __launch_bounds__(THREADS, 4)
void slice_kernel(const float* __restrict__ grid,
                  const float* __restrict__ guide,
                  float* __restrict__ out) {
    extern __shared__ __align__(16) __half yb[];

    const int n   = blockIdx.y;
    const int tid = threadIdx.x;
    const int row = blockIdx.x;            // 1 row per block
    const int x0  = tid * 2;

    // ---- Guide prefetch (streaming; overlaps phase B) ----
    float2 gz = __ldcs(reinterpret_cast<const float2*>(
        guide + (size_t)n * HW + (size_t)row * W + x0));

    // ---- Zero ybuf pads (disjoint from phase-B data writes) ----
    // per z: 16 entries x 2 pad-half2 + 4 slab-pad half2 = 36; 8z = 288; +8 tail
    if (tid < 296) {
        int idx;
        if (tid < 288) {
            int z = tid / 36;
            int t = tid - z * 36;
            int base = z * YSLAB;
            idx = (t < 32) ? base + (t >> 1) * ENTRY + 12 + 2 * (t & 1)
                           : base + GW * ENTRY + 2 * (t - 32);
        } else {
            idx = YROW + 2 * (tid - 288);
        }
        *reinterpret_cast<unsigned*>(yb + idx) = 0u;
    }

    // ---- Phase B: y-lerp this row straight from GMEM (L2-resident grid) ----
    // 192 items: (z, xq4, c2). Each: 4x LDG.128, f32 lerp, 4x STS.32 covering
    // x = 4*xq4..4*xq4+3, channels 2c2, 2c2+1.
    if (tid < 192) {
        int z   = tid / 24;
        int t   = tid - z * 24;
        int xq4 = t / 6;
        int c2  = t - xq4 * 6;

        float ty = (row + 0.5f) * (16.0f / 1024.0f) - 0.5f;
        float fy = floorf(ty);
        float by = ty - fy;
        int ify = (int)fy;
        int iy0 = min(max(ify, 0), GH - 1);
        int iy1 = min(max(ify + 1, 0), GH - 1);
        float wy0f = 1.0f - by, wy1f = by;

        const float* gp = grid + (size_t)n * GRID_PER_N
                        + (size_t)(2 * c2) * 2048 + z * 256 + 4 * xq4;
        float4 a0 = *reinterpret_cast<const float4*>(gp + iy0 * 16);
        float4 b0 = *reinterpret_cast<const float4*>(gp + iy1 * 16);
        float4 a1 = *reinterpret_cast<const float4*>(gp + 2048 + iy0 * 16);
        float4 b1 = *reinterpret_cast<const float4*>(gp + 2048 + iy1 * 16);

        float vA[4] = { a0.x * wy0f + b0.x * wy1f,
                        a0.y * wy0f + b0.y * wy1f,
                        a0.z * wy0f + b0.z * wy1f,
                        a0.w * wy0f + b0.w * wy1f };
        float vB[4] = { a1.x * wy0f + b1.x * wy1f,
                        a1.y * wy0f + b1.y * wy1f,
                        a1.z * wy0f + b1.z * wy1f,
                        a1.w * wy0f + b1.w * wy1f };

        __half* dst = yb + z * YSLAB + (4 * xq4) * ENTRY + 2 * c2;
        #pragma unroll
        for (int i = 0; i < 4; ++i)
            *reinterpret_cast<__half2*>(dst + i * ENTRY) =
                __floats2half2_rn(vA[i], vB[i]);
    }
    __syncthreads();   // the ONLY barrier

    // ---- Phase 3: 2 px/thread, barrier-free ----
    float tx = (x0 + 0.5f) * (1.0f / 64.0f) - 0.5f;
    float fx = floorf(tx);
    int  ifx = (int)fx;
    float bx0 = tx - fx;
    bool edge = (ifx < 0 || ifx >= GW - 1);
    float w1a = edge ? 0.0f : bx0;
    float w1b = edge ? 0.0f : bx0 + (1.0f / 64.0f);
    const int xoff = min(max(ifx, 0), GW - 1) * ENTRY;

    __half2 vz0[6], vz1[6];
    #pragma unroll
    for (int p = 0; p < 2; ++p) {
        float tz = (p ? gz.y : gz.x) * 8.0f - 0.5f;
        float fz = floorf(tz);
        float bz = tz - fz;
        int ifz = (int)fz;
        int iz0 = min(max(ifz, 0), GD - 1);
        int iz1 = min(max(ifz + 1, 0), GD - 1);
        float w1 = p ? w1b : w1a;
        __half2 wx1 = __float2half2_rn(w1);
        __half2 wx0 = __float2half2_rn(1.0f - w1);
        __half2 wz0h = __float2half2_rn(1.0f - bz);
        __half2 wz1h = __float2half2_rn(bz);

        __half2 r0[6], r1[6];
        fetch_xlerp(yb, iz0 * YSLAB + xoff, wx0, wx1, r0);
        fetch_xlerp(yb, iz1 * YSLAB + xoff, wx0, wx1, r1);
        __half2* vz = p ? vz1 : vz0;
        #pragma unroll
        for (int kk = 0; kk < 6; ++kk)
            vz[kk] = __hfma2(r1[kk], wz1h, __hmul2(r0[kk], wz0h));
    }

    float* obr = out + (size_t)n * C * HW + (size_t)row * W + x0;
    #pragma unroll
    for (int kk = 0; kk < 6; ++kk) {
        float2 fa = __half22float2(vz0[kk]);   // (ch 2k,2k+1) px0
        float2 fb = __half22float2(vz1[kk]);   // (ch 2k,2k+1) px1
        float2 lo = make_float2(fa.x, fb.x);
        float2 hi = make_float2(fa.y, fb.y);
        __stcs(reinterpret_cast<float2*>(obr + (size_t)(2 * kk) * HW), lo);
        __stcs(reinterpret_cast<float2*>(obr + (size_t)(2 * kk + 1) * HW), hi);
    }
}

extern "C" void kernel_launch(void* const* d_in, const int* in_sizes, int n_in,
                              void* d_out, int out_size) {
    const float* grid  = (const float*)d_in[0];   // (4,12,8,16,16) f32
    const float* guide = (const float*)d_in[1];   // (4,1,1024,1024) f32
    float* out = (float*)d_out;                   // (4,12,1024,1024) f32

    cudaFuncSetAttribute(slice_kernel,
                         cudaFuncAttributeMaxDynamicSharedMemorySize,
                         SMEM_BYTES);

    dim3 gridDim(H, Nb);                          // (1024, 4) = 4096 blocks
    slice_kernel<<<gridDim, THREADS, SMEM_BYTES>>>(grid, guide, out);
}